// round 12
// baseline (speedup 1.0000x reference)
#include <cuda_runtime.h>
#include <math.h>

#define BATCH 4
#define NPTS  4096
#define KNN   16
#define NB    32          // 2*k neighbors per point
#define NPIX  (BATCH*NPTS*NB)

// ---------------- device scratch ----------------
__device__ float4 g_feats[NPIX];        // (resi.x, resi.y, resi.z, dist) per pixel
__device__ float  g_grp[NPIX*3];        // gathered neighbor coords per pixel
__device__ float4 g_r4[2*BATCH*NPTS];   // prepacked refs: (x, y, z, x^2+y^2+z^2)

// folded + tf32-split weights, padded to k-stride 68 (prep_k fills these)
__device__ float  gW1h[64*68],  gW1l[64*68];
__device__ float  gW2h[128*68], gW2l[128*68];
__device__ float4 gW0f[64];
__device__ float  gb0[64], gb1[64], gb2[128];

// ---------------- helpers ----------------
__device__ __forceinline__ unsigned f2tf(float x) {
    unsigned r; asm("cvt.rna.tf32.f32 %0,%1;" : "=r"(r) : "f"(x)); return r;
}
__device__ __forceinline__ void mma8(float& c0, float& c1, float& c2, float& c3,
                                     unsigned a0, unsigned a1, unsigned a2, unsigned a3,
                                     unsigned b0, unsigned b1)
{
    asm("mma.sync.aligned.m16n8k8.row.col.f32.tf32.tf32.f32 "
        "{%0,%1,%2,%3},{%4,%5,%6,%7},{%8,%9},{%0,%1,%2,%3};"
        : "+f"(c0), "+f"(c1), "+f"(c2), "+f"(c3)
        : "r"(a0), "r"(a1), "r"(a2), "r"(a3), "r"(b0), "r"(b1));
}

// ---------------- pack refs with their squared norm ----------------
__global__ __launch_bounds__(256) void pack_k(const float* __restrict__ p1,
                                              const float* __restrict__ p2)
{
    int i = blockIdx.x * 256 + threadIdx.x;     // 0 .. 2*BATCH*NPTS-1
    int phase = i >> 14;                        // BATCH*NPTS = 16384
    int rem   = i & 16383;
    int b     = rem >> 12;
    int r     = rem & (NPTS - 1);
    const float* P = (phase ? p2 : p1) + b * 3 * NPTS;
    float x = P[r], y = P[NPTS + r], z = P[2*NPTS + r];
    g_r4[i] = make_float4(x, y, z, fmaf(x, x, fmaf(y, y, z * z)));
}

// ---------------- fold BN + split weights into tf32 hi/lo (once) ----------------
__global__ __launch_bounds__(256) void prep_k(
    const float* __restrict__ w0, const float* __restrict__ b0,
    const float* __restrict__ g0, const float* __restrict__ be0,
    const float* __restrict__ m0, const float* __restrict__ v0,
    const float* __restrict__ w1, const float* __restrict__ b1,
    const float* __restrict__ g1, const float* __restrict__ be1,
    const float* __restrict__ m1, const float* __restrict__ v1,
    const float* __restrict__ w2, const float* __restrict__ b2,
    const float* __restrict__ g2, const float* __restrict__ be2,
    const float* __restrict__ m2, const float* __restrict__ v2)
{
    __shared__ float s1[64], s2[128];
    int t = threadIdx.x;
    if (t < 64) {
        float s = g0[t] * rsqrtf(v0[t] + 1e-3f);
        float4 w; w.x = w0[t*4+0]*s; w.y = w0[t*4+1]*s; w.z = w0[t*4+2]*s; w.w = w0[t*4+3]*s;
        gW0f[t] = w;
        gb0[t] = (b0[t] - m0[t]) * s + be0[t];
        float ss = g1[t] * rsqrtf(v1[t] + 1e-3f);
        s1[t] = ss;
        gb1[t] = (b1[t] - m1[t]) * ss + be1[t];
    }
    if (t < 128) {
        float ss = g2[t] * rsqrtf(v2[t] + 1e-3f);
        s2[t] = ss;
        gb2[t] = (b2[t] - m2[t]) * ss + be2[t];
    }
    __syncthreads();
    for (int i = t; i < 64*68; i += 256) {
        int n = i / 68, k = i % 68;
        float wv = (k < 64) ? w1[n*64 + k] * s1[n] : 0.f;
        unsigned h = f2tf(wv);
        float lo = wv - __uint_as_float(h);
        gW1h[i] = __uint_as_float(h);
        gW1l[i] = __uint_as_float(f2tf(lo));
    }
    for (int i = t; i < 128*68; i += 256) {
        int n = i / 68, k = i % 68;
        float wv = (k < 64) ? w2[n*64 + k] * s2[n] : 0.f;
        unsigned h = f2tf(wv);
        float lo = wv - __uint_as_float(h);
        gW2h[i] = __uint_as_float(h);
        gW2l[i] = __uint_as_float(f2tf(lo));
    }
}

// ---------------- KNN: one WARP per query, warp-distributed sorted top-16 ----------------
// (unchanged: validated ~137 us)
#define KTILE 2048

__global__ __launch_bounds__(256) void knn_w(const float* __restrict__ p1)
{
    const int lane  = threadIdx.x & 31;
    const int wid   = threadIdx.x >> 5;
    const int b     = blockIdx.y;
    const int phase = blockIdx.z;
    const int n     = blockIdx.x * 8 + wid;       // query index

    const float* Q = p1 + b * 3 * NPTS;
    const float qx = Q[n], qy = Q[NPTS + n], qz = Q[2*NPTS + n];

    const float4* __restrict__ R4 = g_r4 + (phase * BATCH + b) * NPTS;

    const float INF = __int_as_float(0x7f800000);
    float dl = INF;   // slot (lane) value, v-domain
    int   il = 0;     // slot (lane) ref index

    __shared__ float4 sref[KTILE];

    for (int t0 = 0; t0 < NPTS; t0 += KTILE) {
        for (int i = threadIdx.x; i < KTILE; i += 256)
            sref[i] = R4[t0 + i];
        __syncthreads();

        for (int tt = 0; tt < KTILE / 32; tt++) {
            const int tbase = t0 + tt * 32;
            float4 rv = sref[tt * 32 + lane];
            float dot = fmaf(qx, rv.x, fmaf(qy, rv.y, qz * rv.z));
            float v   = fmaf(-2.f, dot, rv.w);
            float thr = __shfl_sync(0xffffffffu, dl, 15);
            unsigned mask = __ballot_sync(0xffffffffu, v < thr);
            while (mask) {
                int src = __ffs(mask) - 1;
                mask &= mask - 1;
                float c  = __shfl_sync(0xffffffffu, v, src);
                int   ci = tbase + src;
                float up  = __shfl_up_sync(0xffffffffu, dl, 1);
                int   upi = __shfl_up_sync(0xffffffffu, il, 1);
                bool  p   = c < dl;
                unsigned bp = __ballot_sync(0xffffffffu, p);
                bool  pu  = lane ? ((bp >> (lane - 1)) & 1u) : false;
                dl = p ? (pu ? up  : c ) : dl;
                il = p ? (pu ? upi : ci) : il;
            }
        }
        __syncthreads();
    }

    if (lane < KNN) {
        float4 rv = R4[il];
        float dx = rv.x - qx, dy = rv.y - qy, dz = rv.z - qz;
        float d  = sqrtf(fmaxf(dx*dx + dy*dy + dz*dz, 1e-12f));
        size_t base = ((size_t)(b * NPTS + n)) * NB + phase * KNN + lane;
        g_feats[base] = make_float4(dx, dy, dz, d);
        g_grp[base*3 + 0] = rv.x;
        g_grp[base*3 + 1] = rv.y;
        g_grp[base*3 + 2] = rv.z;
    }
}

// ---------------- MLP via tensor cores (tf32 3-split) + max/softmax/sum ----------------
// block = 256 threads = 8 warps, 128 pixels (4 points). Warp w owns pixel rows
// [16w,16w+16). Activations in smem [px][k] stride 68 (conflict-free frags).
// smem float offsets:
#define SME_W1H 0
#define SME_W1L 4352
#define SME_W2H 8704
#define SME_W2L 17408
#define SME_H0  26112
#define SME_H1  34816
#define SME_W0  43520   // float4[64]
#define SME_B0  43776
#define SME_B1  43840
#define SME_B2  43904
#define SME_MX  44032
#define SME_TOT 44160   // floats -> 176640 bytes

__global__ __launch_bounds__(256) void mlp_mma(float* __restrict__ out)
{
    extern __shared__ float sm[];
    const int t    = threadIdx.x;
    const int lane = t & 31;
    const int w    = t >> 5;

    // ---- stage weights (float4 copies; strides are multiples of 4) ----
    {
        float4* s4 = (float4*)sm;
        const float4* a = (const float4*)gW1h;
        const float4* b = (const float4*)gW1l;
        for (int i = t; i < 64*68/4; i += 256) {
            s4[SME_W1H/4 + i] = a[i];
            s4[SME_W1L/4 + i] = b[i];
        }
        const float4* c = (const float4*)gW2h;
        const float4* d = (const float4*)gW2l;
        for (int i = t; i < 128*68/4; i += 256) {
            s4[SME_W2H/4 + i] = c[i];
            s4[SME_W2L/4 + i] = d[i];
        }
        if (t < 64) {
            s4[SME_W0/4 + t] = gW0f[t];
            sm[SME_B0 + t] = gb0[t];
            sm[SME_B1 + t] = gb1[t];
        }
        if (t < 128) sm[SME_B2 + t] = gb2[t];
    }
    __syncthreads();

    // ---- layer 0: 4 -> 64, 2 threads per pixel ----
    {
        int px = t & 127, half = t >> 7;
        float4 x = g_feats[(size_t)blockIdx.x * 128 + px];
        const float4* s4 = (const float4*)sm;
        #pragma unroll 4
        for (int c = 0; c < 32; c++) {
            int ch = half * 32 + c;
            float4 wv = s4[SME_W0/4 + ch];
            float a = fmaf(wv.x, x.x, fmaf(wv.y, x.y,
                      fmaf(wv.z, x.z, fmaf(wv.w, x.w, sm[SME_B0 + ch]))));
            sm[SME_H0 + px*68 + ch] = fmaxf(a, 0.f);
        }
    }
    __syncthreads();

    const int gid = lane >> 2;    // 0..7
    const int tig = lane & 3;     // 0..3
    const int px0 = w * 16;

    // ---- GEMM1: h1[128x64] = relu(h0[128x64] @ W1^T + b1), 3xtf32 ----
    {
        float C[8][4];
        #pragma unroll
        for (int nt = 0; nt < 8; nt++)
            C[nt][0] = C[nt][1] = C[nt][2] = C[nt][3] = 0.f;

        for (int k0 = 0; k0 < 64; k0 += 8) {
            float f0 = sm[SME_H0 + (px0+gid)*68   + k0+tig];
            float f1 = sm[SME_H0 + (px0+gid+8)*68 + k0+tig];
            float f2 = sm[SME_H0 + (px0+gid)*68   + k0+tig+4];
            float f3 = sm[SME_H0 + (px0+gid+8)*68 + k0+tig+4];
            unsigned a0h = f2tf(f0), a1h = f2tf(f1), a2h = f2tf(f2), a3h = f2tf(f3);
            unsigned a0l = f2tf(f0 - __uint_as_float(a0h));
            unsigned a1l = f2tf(f1 - __uint_as_float(a1h));
            unsigned a2l = f2tf(f2 - __uint_as_float(a2h));
            unsigned a3l = f2tf(f3 - __uint_as_float(a3h));
            #pragma unroll
            for (int nt = 0; nt < 8; nt++) {
                int nr = nt * 8 + gid;
                unsigned b0h = __float_as_uint(sm[SME_W1H + nr*68 + k0+tig]);
                unsigned b1h = __float_as_uint(sm[SME_W1H + nr*68 + k0+tig+4]);
                unsigned b0l = __float_as_uint(sm[SME_W1L + nr*68 + k0+tig]);
                unsigned b1l = __float_as_uint(sm[SME_W1L + nr*68 + k0+tig+4]);
                mma8(C[nt][0], C[nt][1], C[nt][2], C[nt][3], a0h, a1h, a2h, a3h, b0h, b1h);
                mma8(C[nt][0], C[nt][1], C[nt][2], C[nt][3], a0h, a1h, a2h, a3h, b0l, b1l);
                mma8(C[nt][0], C[nt][1], C[nt][2], C[nt][3], a0l, a1l, a2l, a3l, b0h, b1h);
            }
        }
        #pragma unroll
        for (int nt = 0; nt < 8; nt++) {
            int ch = nt * 8 + 2 * tig;
            float bA = sm[SME_B1 + ch], bB = sm[SME_B1 + ch + 1];
            sm[SME_H1 + (px0+gid)*68   + ch]     = fmaxf(C[nt][0] + bA, 0.f);
            sm[SME_H1 + (px0+gid)*68   + ch + 1] = fmaxf(C[nt][1] + bB, 0.f);
            sm[SME_H1 + (px0+gid+8)*68 + ch]     = fmaxf(C[nt][2] + bA, 0.f);
            sm[SME_H1 + (px0+gid+8)*68 + ch + 1] = fmaxf(C[nt][3] + bB, 0.f);
        }
    }
    __syncthreads();

    // ---- GEMM2: logits[128x128], fused channel-max ----
    {
        float C[16][4];
        #pragma unroll
        for (int nt = 0; nt < 16; nt++)
            C[nt][0] = C[nt][1] = C[nt][2] = C[nt][3] = 0.f;

        for (int k0 = 0; k0 < 64; k0 += 8) {
            float f0 = sm[SME_H1 + (px0+gid)*68   + k0+tig];
            float f1 = sm[SME_H1 + (px0+gid+8)*68 + k0+tig];
            float f2 = sm[SME_H1 + (px0+gid)*68   + k0+tig+4];
            float f3 = sm[SME_H1 + (px0+gid+8)*68 + k0+tig+4];
            unsigned a0h = f2tf(f0), a1h = f2tf(f1), a2h = f2tf(f2), a3h = f2tf(f3);
            unsigned a0l = f2tf(f0 - __uint_as_float(a0h));
            unsigned a1l = f2tf(f1 - __uint_as_float(a1h));
            unsigned a2l = f2tf(f2 - __uint_as_float(a2h));
            unsigned a3l = f2tf(f3 - __uint_as_float(a3h));
            #pragma unroll
            for (int nt = 0; nt < 16; nt++) {
                int nr = nt * 8 + gid;
                unsigned b0h = __float_as_uint(sm[SME_W2H + nr*68 + k0+tig]);
                unsigned b1h = __float_as_uint(sm[SME_W2H + nr*68 + k0+tig+4]);
                unsigned b0l = __float_as_uint(sm[SME_W2L + nr*68 + k0+tig]);
                unsigned b1l = __float_as_uint(sm[SME_W2L + nr*68 + k0+tig+4]);
                mma8(C[nt][0], C[nt][1], C[nt][2], C[nt][3], a0h, a1h, a2h, a3h, b0h, b1h);
                mma8(C[nt][0], C[nt][1], C[nt][2], C[nt][3], a0h, a1h, a2h, a3h, b0l, b1l);
                mma8(C[nt][0], C[nt][1], C[nt][2], C[nt][3], a0l, a1l, a2l, a3l, b0h, b1h);
            }
        }
        float mx0 = -1e30f, mx1 = -1e30f;
        #pragma unroll
        for (int nt = 0; nt < 16; nt++) {
            int ch = nt * 8 + 2 * tig;
            float bA = sm[SME_B2 + ch], bB = sm[SME_B2 + ch + 1];
            mx0 = fmaxf(mx0, fmaxf(C[nt][0] + bA, 0.f));
            mx0 = fmaxf(mx0, fmaxf(C[nt][1] + bB, 0.f));
            mx1 = fmaxf(mx1, fmaxf(C[nt][2] + bA, 0.f));
            mx1 = fmaxf(mx1, fmaxf(C[nt][3] + bB, 0.f));
        }
        // reduce over the 4 tig lanes of each gid group
        mx0 = fmaxf(mx0, __shfl_xor_sync(0xffffffffu, mx0, 1));
        mx0 = fmaxf(mx0, __shfl_xor_sync(0xffffffffu, mx0, 2));
        mx1 = fmaxf(mx1, __shfl_xor_sync(0xffffffffu, mx1, 1));
        mx1 = fmaxf(mx1, __shfl_xor_sync(0xffffffffu, mx1, 2));
        if (tig == 0) {
            sm[SME_MX + px0 + gid]     = mx0;
            sm[SME_MX + px0 + gid + 8] = mx1;
        }
    }
    __syncthreads();

    // ---- softmax over 32 neighbors + weighted coord sum (warps 0-3, one point each) ----
    if (w < 4) {
        float m = sm[SME_MX + w * 32 + lane];
        float M = m;
        #pragma unroll
        for (int o = 16; o; o >>= 1) M = fmaxf(M, __shfl_xor_sync(0xffffffffu, M, o));
        float e = expf(m - M);
        float S = e;
        #pragma unroll
        for (int o = 16; o; o >>= 1) S += __shfl_xor_sync(0xffffffffu, S, o);
        float wt = e / S;

        size_t gpix = ((size_t)blockIdx.x * 128 + w * 32 + lane) * 3;
        float sx = wt * g_grp[gpix + 0];
        float sy = wt * g_grp[gpix + 1];
        float sz = wt * g_grp[gpix + 2];
        #pragma unroll
        for (int o = 16; o; o >>= 1) {
            sx += __shfl_xor_sync(0xffffffffu, sx, o);
            sy += __shfl_xor_sync(0xffffffffu, sy, o);
            sz += __shfl_xor_sync(0xffffffffu, sz, o);
        }
        if (lane == 0) {
            int pt = blockIdx.x * 4 + w;
            int b  = pt >> 12;
            int n  = pt & (NPTS - 1);
            out[(b*3 + 0) * NPTS + n] = sx;
            out[(b*3 + 1) * NPTS + n] = sy;
            out[(b*3 + 2) * NPTS + n] = sz;
        }
    }
}

// ---------------- launch ----------------
extern "C" void kernel_launch(void* const* d_in, const int* in_sizes, int n_in,
                              void* d_out, int out_size)
{
    const float* p1 = (const float*)d_in[0];
    const float* p2 = (const float*)d_in[1];
    // d_in[2] = k (fixed at 16)
    const float* w0  = (const float*)d_in[3];
    const float* b0  = (const float*)d_in[4];
    const float* g0  = (const float*)d_in[5];
    const float* be0 = (const float*)d_in[6];
    const float* m0  = (const float*)d_in[7];
    const float* v0  = (const float*)d_in[8];
    const float* w1  = (const float*)d_in[9];
    const float* b1  = (const float*)d_in[10];
    const float* g1  = (const float*)d_in[11];
    const float* be1 = (const float*)d_in[12];
    const float* m1  = (const float*)d_in[13];
    const float* v1  = (const float*)d_in[14];
    const float* w2  = (const float*)d_in[15];
    const float* b2  = (const float*)d_in[16];
    const float* g2  = (const float*)d_in[17];
    const float* be2 = (const float*)d_in[18];
    const float* m2  = (const float*)d_in[19];
    const float* v2  = (const float*)d_in[20];

    cudaFuncSetAttribute(mlp_mma, cudaFuncAttributeMaxDynamicSharedMemorySize,
                         SME_TOT * (int)sizeof(float));

    prep_k<<<1, 256>>>(w0, b0, g0, be0, m0, v0,
                       w1, b1, g1, be1, m1, v1,
                       w2, b2, g2, be2, m2, v2);

    pack_k<<<2*BATCH*NPTS/256, 256>>>(p1, p2);

    knn_w<<<dim3(NPTS/8, BATCH, 2), 256>>>(p1);

    // 128 pixels per block over all NPIX pixels -> NPIX/128 = 4096 blocks
    mlp_mma<<<NPIX/128, 256, SME_TOT * (int)sizeof(float)>>>((float*)d_out);
}

// round 13
// speedup vs baseline: 1.4428x; 1.4428x over previous
#include <cuda_runtime.h>
#include <math.h>

#define BATCH 4
#define NPTS  4096
#define KNN   16
#define NB    32          // 2*k neighbors per point
#define NPIX  (BATCH*NPTS*NB)
#define NTILE (NPIX/128)  // 4096 tiles of 128 pixels

// ---------------- device scratch ----------------
__device__ float4 g_feats[NPIX];        // (resi.x, resi.y, resi.z, dist) per pixel
__device__ float  g_grp[NPIX*3];        // gathered neighbor coords per pixel
__device__ float4 g_r4[2*BATCH*NPTS];   // prepacked refs: (x, y, z, x^2+y^2+z^2)

// folded + tf32-split weights, padded to k-stride 68 (prep_k fills these)
__device__ float  gW1h[64*68],  gW1l[64*68];
__device__ float  gW2h[128*68];
__device__ float4 gW0f[64];
__device__ float  gb0[64], gb1[64], gb2[128];

// ---------------- helpers ----------------
__device__ __forceinline__ unsigned f2tf(float x) {
    unsigned r; asm("cvt.rna.tf32.f32 %0,%1;" : "=r"(r) : "f"(x)); return r;
}
__device__ __forceinline__ void mma8(float& c0, float& c1, float& c2, float& c3,
                                     unsigned a0, unsigned a1, unsigned a2, unsigned a3,
                                     unsigned b0, unsigned b1)
{
    asm("mma.sync.aligned.m16n8k8.row.col.f32.tf32.tf32.f32 "
        "{%0,%1,%2,%3},{%4,%5,%6,%7},{%8,%9},{%0,%1,%2,%3};"
        : "+f"(c0), "+f"(c1), "+f"(c2), "+f"(c3)
        : "r"(a0), "r"(a1), "r"(a2), "r"(a3), "r"(b0), "r"(b1));
}

// ---------------- pack refs with their squared norm ----------------
__global__ __launch_bounds__(256) void pack_k(const float* __restrict__ p1,
                                              const float* __restrict__ p2)
{
    int i = blockIdx.x * 256 + threadIdx.x;     // 0 .. 2*BATCH*NPTS-1
    int phase = i >> 14;                        // BATCH*NPTS = 16384
    int rem   = i & 16383;
    int b     = rem >> 12;
    int r     = rem & (NPTS - 1);
    const float* P = (phase ? p2 : p1) + b * 3 * NPTS;
    float x = P[r], y = P[NPTS + r], z = P[2*NPTS + r];
    g_r4[i] = make_float4(x, y, z, fmaf(x, x, fmaf(y, y, z * z)));
}

// ---------------- fold BN + split weights into tf32 (parallel, 51 blocks) ----------------
__global__ __launch_bounds__(256) void prep_k(
    const float* __restrict__ w0, const float* __restrict__ b0,
    const float* __restrict__ g0, const float* __restrict__ be0,
    const float* __restrict__ m0, const float* __restrict__ v0,
    const float* __restrict__ w1, const float* __restrict__ b1,
    const float* __restrict__ g1, const float* __restrict__ be1,
    const float* __restrict__ m1, const float* __restrict__ v1,
    const float* __restrict__ w2, const float* __restrict__ b2,
    const float* __restrict__ g2, const float* __restrict__ be2,
    const float* __restrict__ m2, const float* __restrict__ v2)
{
    int t = threadIdx.x;
    if (blockIdx.x == 0) {
        if (t < 64) {
            float s = g0[t] * rsqrtf(v0[t] + 1e-3f);
            float4 w; w.x = w0[t*4+0]*s; w.y = w0[t*4+1]*s; w.z = w0[t*4+2]*s; w.w = w0[t*4+3]*s;
            gW0f[t] = w;
            gb0[t] = (b0[t] - m0[t]) * s + be0[t];
            float ss = g1[t] * rsqrtf(v1[t] + 1e-3f);
            gb1[t] = (b1[t] - m1[t]) * ss + be1[t];
        }
        if (t < 128) {
            float ss = g2[t] * rsqrtf(v2[t] + 1e-3f);
            gb2[t] = (b2[t] - m2[t]) * ss + be2[t];
        }
    }
    int i = blockIdx.x * 256 + t;   // 0..13055 covers W1(4352) + W2(8704)
    if (i < 64*68) {
        int n = i / 68, k = i % 68;
        float s = g1[n] * rsqrtf(v1[n] + 1e-3f);
        float wv = (k < 64) ? w1[n*64 + k] * s : 0.f;
        unsigned h = f2tf(wv);
        float lo = wv - __uint_as_float(h);
        gW1h[i] = __uint_as_float(h);
        gW1l[i] = __uint_as_float(f2tf(lo));
    } else if (i < 64*68 + 128*68) {
        int j = i - 64*68;
        int n = j / 68, k = j % 68;
        float s = g2[n] * rsqrtf(v2[n] + 1e-3f);
        float wv = (k < 64) ? w2[n*64 + k] * s : 0.f;
        gW2h[j] = __uint_as_float(f2tf(wv));
    }
}

// ---------------- KNN: one WARP per query, warp-distributed sorted top-16 ----------------
// (unchanged: validated ~137 us)
#define KTILE 2048

__global__ __launch_bounds__(256) void knn_w(const float* __restrict__ p1)
{
    const int lane  = threadIdx.x & 31;
    const int wid   = threadIdx.x >> 5;
    const int b     = blockIdx.y;
    const int phase = blockIdx.z;
    const int n     = blockIdx.x * 8 + wid;       // query index

    const float* Q = p1 + b * 3 * NPTS;
    const float qx = Q[n], qy = Q[NPTS + n], qz = Q[2*NPTS + n];

    const float4* __restrict__ R4 = g_r4 + (phase * BATCH + b) * NPTS;

    const float INF = __int_as_float(0x7f800000);
    float dl = INF;   // slot (lane) value, v-domain
    int   il = 0;     // slot (lane) ref index

    __shared__ float4 sref[KTILE];

    for (int t0 = 0; t0 < NPTS; t0 += KTILE) {
        for (int i = threadIdx.x; i < KTILE; i += 256)
            sref[i] = R4[t0 + i];
        __syncthreads();

        for (int tt = 0; tt < KTILE / 32; tt++) {
            const int tbase = t0 + tt * 32;
            float4 rv = sref[tt * 32 + lane];
            float dot = fmaf(qx, rv.x, fmaf(qy, rv.y, qz * rv.z));
            float v   = fmaf(-2.f, dot, rv.w);
            float thr = __shfl_sync(0xffffffffu, dl, 15);
            unsigned mask = __ballot_sync(0xffffffffu, v < thr);
            while (mask) {
                int src = __ffs(mask) - 1;
                mask &= mask - 1;
                float c  = __shfl_sync(0xffffffffu, v, src);
                int   ci = tbase + src;
                float up  = __shfl_up_sync(0xffffffffu, dl, 1);
                int   upi = __shfl_up_sync(0xffffffffu, il, 1);
                bool  p   = c < dl;
                unsigned bp = __ballot_sync(0xffffffffu, p);
                bool  pu  = lane ? ((bp >> (lane - 1)) & 1u) : false;
                dl = p ? (pu ? up  : c ) : dl;
                il = p ? (pu ? upi : ci) : il;
            }
        }
        __syncthreads();
    }

    if (lane < KNN) {
        float4 rv = R4[il];
        float dx = rv.x - qx, dy = rv.y - qy, dz = rv.z - qz;
        float d  = sqrtf(fmaxf(dx*dx + dy*dy + dz*dz, 1e-12f));
        size_t base = ((size_t)(b * NPTS + n)) * NB + phase * KNN + lane;
        g_feats[base] = make_float4(dx, dy, dz, d);
        g_grp[base*3 + 0] = rv.x;
        g_grp[base*3 + 1] = rv.y;
        g_grp[base*3 + 2] = rv.z;
    }
}

// ---------------- MLP via tensor cores, persistent grid, 2 blocks/SM ----------------
// block = 256 threads = 8 warps; tile = 128 pixels (4 points); warp w owns rows
// [16w,16w+16), which are warp-private through layer0/GEMM1/GEMM2 (H1 aliases H0).
// GEMM1: 3xtf32 (W1 hi+lo). GEMM2: 2-split (AhBh + AlBh), W2 hi only.
// smem float offsets:
#define SW1H 0
#define SW1L 4352
#define SW2H 8704
#define SH   17408     // h0, then h1 aliased (128 x stride 68)
#define SW0  26112     // float4[64]
#define SB0  26368
#define SB1  26432
#define SB2  26496
#define SMX  26624     // double-buffered 2 x 128
#define STOT 26880     // floats -> 107520 bytes

__global__ __launch_bounds__(256, 2) void mlp_mma(float* __restrict__ out)
{
    extern __shared__ float sm[];
    const int t    = threadIdx.x;
    const int lane = t & 31;
    const int w    = t >> 5;

    // ---- stage weights once per block ----
    {
        float4* s4 = (float4*)sm;
        const float4* a = (const float4*)gW1h;
        const float4* b = (const float4*)gW1l;
        for (int i = t; i < 64*68/4; i += 256) {
            s4[SW1H/4 + i] = a[i];
            s4[SW1L/4 + i] = b[i];
        }
        const float4* c = (const float4*)gW2h;
        for (int i = t; i < 128*68/4; i += 256)
            s4[SW2H/4 + i] = c[i];
        if (t < 64) {
            s4[SW0/4 + t] = gW0f[t];
            sm[SB0 + t] = gb0[t];
            sm[SB1 + t] = gb1[t];
        }
        if (t < 128) sm[SB2 + t] = gb2[t];
    }
    __syncthreads();

    const int gid = lane >> 2;    // 0..7
    const int tig = lane & 3;     // 0..3
    const int px0 = w * 16;
    int pb = 0;                   // MX buffer parity

    for (int tile = blockIdx.x; tile < NTILE; tile += gridDim.x) {

        // ---- layer 0 (warp-local): lane handles row px0+(lane&15), half lane>>4 ----
        {
            int rloc = lane & 15, half = lane >> 4;
            int row  = px0 + rloc;
            float4 x = g_feats[(size_t)tile * 128 + row];
            const float4* s4 = (const float4*)sm;
            float* hrow = sm + SH + row * 68 + half * 32;
            #pragma unroll 4
            for (int c = 0; c < 32; c++) {
                int ch = half * 32 + c;
                float4 wv = s4[SW0/4 + ch];
                float a = fmaf(wv.x, x.x, fmaf(wv.y, x.y,
                          fmaf(wv.z, x.z, fmaf(wv.w, x.w, sm[SB0 + ch]))));
                hrow[c] = fmaxf(a, 0.f);
            }
        }
        __syncwarp();

        // ---- GEMM1: h1 = relu(h0 @ W1^T + b1), 3xtf32, H1 aliases H0 ----
        {
            float C[8][4];
            #pragma unroll
            for (int nt = 0; nt < 8; nt++)
                C[nt][0] = C[nt][1] = C[nt][2] = C[nt][3] = 0.f;

            for (int k0 = 0; k0 < 64; k0 += 8) {
                float f0 = sm[SH + (px0+gid)*68   + k0+tig];
                float f1 = sm[SH + (px0+gid+8)*68 + k0+tig];
                float f2 = sm[SH + (px0+gid)*68   + k0+tig+4];
                float f3 = sm[SH + (px0+gid+8)*68 + k0+tig+4];
                unsigned a0h = f2tf(f0), a1h = f2tf(f1), a2h = f2tf(f2), a3h = f2tf(f3);
                unsigned a0l = f2tf(f0 - __uint_as_float(a0h));
                unsigned a1l = f2tf(f1 - __uint_as_float(a1h));
                unsigned a2l = f2tf(f2 - __uint_as_float(a2h));
                unsigned a3l = f2tf(f3 - __uint_as_float(a3h));
                #pragma unroll
                for (int nt = 0; nt < 8; nt++) {
                    int nr = nt * 8 + gid;
                    unsigned b0h = __float_as_uint(sm[SW1H + nr*68 + k0+tig]);
                    unsigned b1h = __float_as_uint(sm[SW1H + nr*68 + k0+tig+4]);
                    unsigned b0l = __float_as_uint(sm[SW1L + nr*68 + k0+tig]);
                    unsigned b1l = __float_as_uint(sm[SW1L + nr*68 + k0+tig+4]);
                    mma8(C[nt][0], C[nt][1], C[nt][2], C[nt][3], a0h, a1h, a2h, a3h, b0h, b1h);
                    mma8(C[nt][0], C[nt][1], C[nt][2], C[nt][3], a0h, a1h, a2h, a3h, b0l, b1l);
                    mma8(C[nt][0], C[nt][1], C[nt][2], C[nt][3], a0l, a1l, a2l, a3l, b0h, b1h);
                }
            }
            __syncwarp();   // all h0 reads done before aliased h1 writes
            #pragma unroll
            for (int nt = 0; nt < 8; nt++) {
                int ch = nt * 8 + 2 * tig;
                float bA = sm[SB1 + ch], bB = sm[SB1 + ch + 1];
                sm[SH + (px0+gid)*68   + ch]     = fmaxf(C[nt][0] + bA, 0.f);
                sm[SH + (px0+gid)*68   + ch + 1] = fmaxf(C[nt][1] + bB, 0.f);
                sm[SH + (px0+gid+8)*68 + ch]     = fmaxf(C[nt][2] + bA, 0.f);
                sm[SH + (px0+gid+8)*68 + ch + 1] = fmaxf(C[nt][3] + bB, 0.f);
            }
        }
        __syncwarp();

        // ---- GEMM2: logits, 2-split (AhBh + AlBh), fused channel-max ----
        {
            float C[16][4];
            #pragma unroll
            for (int nt = 0; nt < 16; nt++)
                C[nt][0] = C[nt][1] = C[nt][2] = C[nt][3] = 0.f;

            for (int k0 = 0; k0 < 64; k0 += 8) {
                float f0 = sm[SH + (px0+gid)*68   + k0+tig];
                float f1 = sm[SH + (px0+gid+8)*68 + k0+tig];
                float f2 = sm[SH + (px0+gid)*68   + k0+tig+4];
                float f3 = sm[SH + (px0+gid+8)*68 + k0+tig+4];
                unsigned a0h = f2tf(f0), a1h = f2tf(f1), a2h = f2tf(f2), a3h = f2tf(f3);
                unsigned a0l = f2tf(f0 - __uint_as_float(a0h));
                unsigned a1l = f2tf(f1 - __uint_as_float(a1h));
                unsigned a2l = f2tf(f2 - __uint_as_float(a2h));
                unsigned a3l = f2tf(f3 - __uint_as_float(a3h));
                #pragma unroll
                for (int nt = 0; nt < 16; nt++) {
                    int nr = nt * 8 + gid;
                    unsigned b0h = __float_as_uint(sm[SW2H + nr*68 + k0+tig]);
                    unsigned b1h = __float_as_uint(sm[SW2H + nr*68 + k0+tig+4]);
                    mma8(C[nt][0], C[nt][1], C[nt][2], C[nt][3], a0h, a1h, a2h, a3h, b0h, b1h);
                    mma8(C[nt][0], C[nt][1], C[nt][2], C[nt][3], a0l, a1l, a2l, a3l, b0h, b1h);
                }
            }
            float mx0 = -1e30f, mx1 = -1e30f;
            #pragma unroll
            for (int nt = 0; nt < 16; nt++) {
                int ch = nt * 8 + 2 * tig;
                float bA = sm[SB2 + ch], bB = sm[SB2 + ch + 1];
                mx0 = fmaxf(mx0, fmaxf(C[nt][0] + bA, 0.f));
                mx0 = fmaxf(mx0, fmaxf(C[nt][1] + bB, 0.f));
                mx1 = fmaxf(mx1, fmaxf(C[nt][2] + bA, 0.f));
                mx1 = fmaxf(mx1, fmaxf(C[nt][3] + bB, 0.f));
            }
            mx0 = fmaxf(mx0, __shfl_xor_sync(0xffffffffu, mx0, 1));
            mx0 = fmaxf(mx0, __shfl_xor_sync(0xffffffffu, mx0, 2));
            mx1 = fmaxf(mx1, __shfl_xor_sync(0xffffffffu, mx1, 1));
            mx1 = fmaxf(mx1, __shfl_xor_sync(0xffffffffu, mx1, 2));
            if (tig == 0) {
                sm[SMX + pb*128 + px0 + gid]     = mx0;
                sm[SMX + pb*128 + px0 + gid + 8] = mx1;
            }
        }
        __syncthreads();

        // ---- softmax over 32 neighbors + weighted coord sum (warps 0-3) ----
        if (w < 4) {
            float m = sm[SMX + pb*128 + w * 32 + lane];
            float M = m;
            #pragma unroll
            for (int o = 16; o; o >>= 1) M = fmaxf(M, __shfl_xor_sync(0xffffffffu, M, o));
            float e = expf(m - M);
            float S = e;
            #pragma unroll
            for (int o = 16; o; o >>= 1) S += __shfl_xor_sync(0xffffffffu, S, o);
            float wt = e / S;

            size_t gpix = ((size_t)tile * 128 + w * 32 + lane) * 3;
            float sx = wt * g_grp[gpix + 0];
            float sy = wt * g_grp[gpix + 1];
            float sz = wt * g_grp[gpix + 2];
            #pragma unroll
            for (int o = 16; o; o >>= 1) {
                sx += __shfl_xor_sync(0xffffffffu, sx, o);
                sy += __shfl_xor_sync(0xffffffffu, sy, o);
                sz += __shfl_xor_sync(0xffffffffu, sz, o);
            }
            if (lane == 0) {
                int pt = tile * 4 + w;
                int b  = pt >> 12;
                int n  = pt & (NPTS - 1);
                out[(b*3 + 0) * NPTS + n] = sx;
                out[(b*3 + 1) * NPTS + n] = sy;
                out[(b*3 + 2) * NPTS + n] = sz;
            }
        }
        pb ^= 1;
    }
}

// ---------------- launch ----------------
extern "C" void kernel_launch(void* const* d_in, const int* in_sizes, int n_in,
                              void* d_out, int out_size)
{
    const float* p1 = (const float*)d_in[0];
    const float* p2 = (const float*)d_in[1];
    // d_in[2] = k (fixed at 16)
    const float* w0  = (const float*)d_in[3];
    const float* b0  = (const float*)d_in[4];
    const float* g0  = (const float*)d_in[5];
    const float* be0 = (const float*)d_in[6];
    const float* m0  = (const float*)d_in[7];
    const float* v0  = (const float*)d_in[8];
    const float* w1  = (const float*)d_in[9];
    const float* b1  = (const float*)d_in[10];
    const float* g1  = (const float*)d_in[11];
    const float* be1 = (const float*)d_in[12];
    const float* m1  = (const float*)d_in[13];
    const float* v1  = (const float*)d_in[14];
    const float* w2  = (const float*)d_in[15];
    const float* b2  = (const float*)d_in[16];
    const float* g2  = (const float*)d_in[17];
    const float* be2 = (const float*)d_in[18];
    const float* m2  = (const float*)d_in[19];
    const float* v2  = (const float*)d_in[20];

    cudaFuncSetAttribute(mlp_mma, cudaFuncAttributeMaxDynamicSharedMemorySize,
                         STOT * (int)sizeof(float));

    prep_k<<<51, 256>>>(w0, b0, g0, be0, m0, v0,
                        w1, b1, g1, be1, m1, v1,
                        w2, b2, g2, be2, m2, v2);

    pack_k<<<2*BATCH*NPTS/256, 256>>>(p1, p2);

    knn_w<<<dim3(NPTS/8, BATCH, 2), 256>>>(p1);

    // persistent: 2 blocks/SM on 148 SMs
    mlp_mma<<<296, 256, STOT * (int)sizeof(float)>>>((float*)d_out);
}

// round 14
// speedup vs baseline: 1.5225x; 1.0553x over previous
#include <cuda_runtime.h>
#include <math.h>

#define BATCH 4
#define NPTS  4096
#define KNN   16
#define NB    32          // 2*k neighbors per point
#define NPIX  (BATCH*NPTS*NB)
#define NTILE (NPIX/128)  // 4096 tiles of 128 pixels

// ---------------- device scratch ----------------
__device__ float4 g_feats[NPIX];        // (resi.x, resi.y, resi.z, dist) per pixel
__device__ float  g_grp[NPIX*3];        // gathered neighbor coords per pixel
__device__ float4 g_r4[2*BATCH*NPTS];   // prepacked refs: (x, y, z, x^2+y^2+z^2)

// folded weights in PAIRED tf32 layout: row nr holds float2 pairs
// pw[nr*36 + (k>>1 of k0) + tig] = (w[8j+tig], w[8j+4+tig]); row stride 72 floats
__device__ float  gW1hp[64*72], gW1lp[64*72];
__device__ float  gW2hp[128*72];
__device__ float4 gW0f[64];
__device__ float  gb0[64], gb1[64], gb2[128];

// ---------------- helpers ----------------
__device__ __forceinline__ unsigned f2tf(float x) {
    unsigned r; asm("cvt.rna.tf32.f32 %0,%1;" : "=r"(r) : "f"(x)); return r;
}
__device__ __forceinline__ void mma8(float& c0, float& c1, float& c2, float& c3,
                                     unsigned a0, unsigned a1, unsigned a2, unsigned a3,
                                     unsigned b0, unsigned b1)
{
    asm("mma.sync.aligned.m16n8k8.row.col.f32.tf32.tf32.f32 "
        "{%0,%1,%2,%3},{%4,%5,%6,%7},{%8,%9},{%0,%1,%2,%3};"
        : "+f"(c0), "+f"(c1), "+f"(c2), "+f"(c3)
        : "r"(a0), "r"(a1), "r"(a2), "r"(a3), "r"(b0), "r"(b1));
}
// paired index for weight element k (0..63): j=k>>3, tig=k&3, slot=(k>>2)&1
__device__ __forceinline__ int pidx(int nr, int k) {
    return nr * 72 + (((k >> 3) * 4 + (k & 3)) << 1) + ((k >> 2) & 1);
}

// ---------------- pack refs with their squared norm ----------------
__global__ __launch_bounds__(256) void pack_k(const float* __restrict__ p1,
                                              const float* __restrict__ p2)
{
    int i = blockIdx.x * 256 + threadIdx.x;     // 0 .. 2*BATCH*NPTS-1
    int phase = i >> 14;                        // BATCH*NPTS = 16384
    int rem   = i & 16383;
    int b     = rem >> 12;
    int r     = rem & (NPTS - 1);
    const float* P = (phase ? p2 : p1) + b * 3 * NPTS;
    float x = P[r], y = P[NPTS + r], z = P[2*NPTS + r];
    g_r4[i] = make_float4(x, y, z, fmaf(x, x, fmaf(y, y, z * z)));
}

// ---------------- fold BN + split weights into paired tf32 (parallel) ----------------
__global__ __launch_bounds__(256) void prep_k(
    const float* __restrict__ w0, const float* __restrict__ b0,
    const float* __restrict__ g0, const float* __restrict__ be0,
    const float* __restrict__ m0, const float* __restrict__ v0,
    const float* __restrict__ w1, const float* __restrict__ b1,
    const float* __restrict__ g1, const float* __restrict__ be1,
    const float* __restrict__ m1, const float* __restrict__ v1,
    const float* __restrict__ w2, const float* __restrict__ b2,
    const float* __restrict__ g2, const float* __restrict__ be2,
    const float* __restrict__ m2, const float* __restrict__ v2)
{
    int t = threadIdx.x;
    if (blockIdx.x == 0) {
        if (t < 64) {
            float s = g0[t] * rsqrtf(v0[t] + 1e-3f);
            float4 w; w.x = w0[t*4+0]*s; w.y = w0[t*4+1]*s; w.z = w0[t*4+2]*s; w.w = w0[t*4+3]*s;
            gW0f[t] = w;
            gb0[t] = (b0[t] - m0[t]) * s + be0[t];
            float ss = g1[t] * rsqrtf(v1[t] + 1e-3f);
            gb1[t] = (b1[t] - m1[t]) * ss + be1[t];
        }
        if (t < 128) {
            float ss = g2[t] * rsqrtf(v2[t] + 1e-3f);
            gb2[t] = (b2[t] - m2[t]) * ss + be2[t];
        }
    }
    int i = blockIdx.x * 256 + t;   // W1: 64x64=4096 elems, W2: 128x64=8192 elems
    if (i < 4096) {
        int nr = i >> 6, k = i & 63;
        float s = g1[nr] * rsqrtf(v1[nr] + 1e-3f);
        float wv = w1[nr*64 + k] * s;
        unsigned h = f2tf(wv);
        float lo = wv - __uint_as_float(h);
        int p = pidx(nr, k);
        gW1hp[p] = __uint_as_float(h);
        gW1lp[p] = __uint_as_float(f2tf(lo));
    } else if (i < 4096 + 8192) {
        int j = i - 4096;
        int nr = j >> 6, k = j & 63;
        float s = g2[nr] * rsqrtf(v2[nr] + 1e-3f);
        float wv = w2[nr*64 + k] * s;
        gW2hp[pidx(nr, k)] = __uint_as_float(f2tf(wv));
    }
}

// ---------------- KNN: one WARP per query, warp-distributed sorted top-16 ----------------
// (unchanged: validated ~137 us)
#define KTILE 2048

__global__ __launch_bounds__(256) void knn_w(const float* __restrict__ p1)
{
    const int lane  = threadIdx.x & 31;
    const int wid   = threadIdx.x >> 5;
    const int b     = blockIdx.y;
    const int phase = blockIdx.z;
    const int n     = blockIdx.x * 8 + wid;       // query index

    const float* Q = p1 + b * 3 * NPTS;
    const float qx = Q[n], qy = Q[NPTS + n], qz = Q[2*NPTS + n];

    const float4* __restrict__ R4 = g_r4 + (phase * BATCH + b) * NPTS;

    const float INF = __int_as_float(0x7f800000);
    float dl = INF;   // slot (lane) value, v-domain
    int   il = 0;     // slot (lane) ref index

    __shared__ float4 sref[KTILE];

    for (int t0 = 0; t0 < NPTS; t0 += KTILE) {
        for (int i = threadIdx.x; i < KTILE; i += 256)
            sref[i] = R4[t0 + i];
        __syncthreads();

        for (int tt = 0; tt < KTILE / 32; tt++) {
            const int tbase = t0 + tt * 32;
            float4 rv = sref[tt * 32 + lane];
            float dot = fmaf(qx, rv.x, fmaf(qy, rv.y, qz * rv.z));
            float v   = fmaf(-2.f, dot, rv.w);
            float thr = __shfl_sync(0xffffffffu, dl, 15);
            unsigned mask = __ballot_sync(0xffffffffu, v < thr);
            while (mask) {
                int src = __ffs(mask) - 1;
                mask &= mask - 1;
                float c  = __shfl_sync(0xffffffffu, v, src);
                int   ci = tbase + src;
                float up  = __shfl_up_sync(0xffffffffu, dl, 1);
                int   upi = __shfl_up_sync(0xffffffffu, il, 1);
                bool  p   = c < dl;
                unsigned bp = __ballot_sync(0xffffffffu, p);
                bool  pu  = lane ? ((bp >> (lane - 1)) & 1u) : false;
                dl = p ? (pu ? up  : c ) : dl;
                il = p ? (pu ? upi : ci) : il;
            }
        }
        __syncthreads();
    }

    if (lane < KNN) {
        float4 rv = R4[il];
        float dx = rv.x - qx, dy = rv.y - qy, dz = rv.z - qz;
        float d  = sqrtf(fmaxf(dx*dx + dy*dy + dz*dz, 1e-12f));
        size_t base = ((size_t)(b * NPTS + n)) * NB + phase * KNN + lane;
        g_feats[base] = make_float4(dx, dy, dz, d);
        g_grp[base*3 + 0] = rv.x;
        g_grp[base*3 + 1] = rv.y;
        g_grp[base*3 + 2] = rv.z;
    }
}

// ---------------- MLP via tensor cores, persistent grid, 2 blocks/SM ----------------
// block = 256 threads = 8 warps; tile = 128 pixels (4 points); warp w owns rows
// [16w,16w+16) (warp-private; H1 aliases H0). Weights in paired float2 layout:
// one LDS.64 per B-fragment (b0=pair.x at k0+tig, b1=pair.y at k0+tig+4).
// GEMM1: 3xtf32. GEMM2: 2-split (AhBh + AlBh).
// smem float offsets:
#define SW1H 0          // 64 x 72
#define SW1L 4608
#define SW2H 9216       // 128 x 72
#define SH   18432      // h0 / h1 aliased (128 x stride 68)
#define SW0  27136      // float4[64]
#define SB0  27392
#define SB1  27456
#define SB2  27520
#define SMX  27648      // double-buffered 2 x 128
#define STOT 27904      // floats -> 111616 bytes

__global__ __launch_bounds__(256, 2) void mlp_mma(float* __restrict__ out)
{
    extern __shared__ float sm[];
    const int t    = threadIdx.x;
    const int lane = t & 31;
    const int w    = t >> 5;

    // ---- stage weights once per block ----
    {
        float4* s4 = (float4*)sm;
        const float4* a = (const float4*)gW1hp;
        const float4* b = (const float4*)gW1lp;
        for (int i = t; i < 64*72/4; i += 256) {
            s4[SW1H/4 + i] = a[i];
            s4[SW1L/4 + i] = b[i];
        }
        const float4* c = (const float4*)gW2hp;
        for (int i = t; i < 128*72/4; i += 256)
            s4[SW2H/4 + i] = c[i];
        if (t < 64) {
            s4[SW0/4 + t] = gW0f[t];
            sm[SB0 + t] = gb0[t];
            sm[SB1 + t] = gb1[t];
        }
        if (t < 128) sm[SB2 + t] = gb2[t];
    }
    __syncthreads();

    const int gid = lane >> 2;    // 0..7
    const int tig = lane & 3;     // 0..3
    const int px0 = w * 16;
    int pb = 0;                   // MX buffer parity

    const float2* W1H2 = (const float2*)(sm + SW1H);
    const float2* W1L2 = (const float2*)(sm + SW1L);
    const float2* W2H2 = (const float2*)(sm + SW2H);

    for (int tile = blockIdx.x; tile < NTILE; tile += gridDim.x) {

        // ---- layer 0 (warp-local): lane handles row px0+(lane&15), half lane>>4 ----
        {
            int rloc = lane & 15, half = lane >> 4;
            int row  = px0 + rloc;
            float4 x = g_feats[(size_t)tile * 128 + row];
            const float4* s4 = (const float4*)sm;
            float* hrow = sm + SH + row * 68 + half * 32;
            #pragma unroll 4
            for (int c = 0; c < 32; c++) {
                int ch = half * 32 + c;
                float4 wv = s4[SW0/4 + ch];
                float a = fmaf(wv.x, x.x, fmaf(wv.y, x.y,
                          fmaf(wv.z, x.z, fmaf(wv.w, x.w, sm[SB0 + ch]))));
                hrow[c] = fmaxf(a, 0.f);
            }
        }
        __syncwarp();

        // ---- GEMM1: h1 = relu(h0 @ W1^T + b1), 3xtf32, H1 aliases H0 ----
        {
            float C[8][4];
            #pragma unroll
            for (int nt = 0; nt < 8; nt++)
                C[nt][0] = C[nt][1] = C[nt][2] = C[nt][3] = 0.f;

            for (int k0 = 0; k0 < 64; k0 += 8) {
                const int pp = (k0 >> 1) + tig;     // paired index within row
                float f0 = sm[SH + (px0+gid)*68   + k0+tig];
                float f1 = sm[SH + (px0+gid+8)*68 + k0+tig];
                float f2 = sm[SH + (px0+gid)*68   + k0+tig+4];
                float f3 = sm[SH + (px0+gid+8)*68 + k0+tig+4];
                unsigned a0h = f2tf(f0), a1h = f2tf(f1), a2h = f2tf(f2), a3h = f2tf(f3);
                unsigned a0l = f2tf(f0 - __uint_as_float(a0h));
                unsigned a1l = f2tf(f1 - __uint_as_float(a1h));
                unsigned a2l = f2tf(f2 - __uint_as_float(a2h));
                unsigned a3l = f2tf(f3 - __uint_as_float(a3h));
                #pragma unroll
                for (int nt = 0; nt < 8; nt++) {
                    int nr = nt * 8 + gid;
                    float2 bh = W1H2[nr*36 + pp];
                    float2 bl = W1L2[nr*36 + pp];
                    unsigned b0h = __float_as_uint(bh.x), b1h = __float_as_uint(bh.y);
                    unsigned b0l = __float_as_uint(bl.x), b1l = __float_as_uint(bl.y);
                    mma8(C[nt][0], C[nt][1], C[nt][2], C[nt][3], a0h, a1h, a2h, a3h, b0h, b1h);
                    mma8(C[nt][0], C[nt][1], C[nt][2], C[nt][3], a0h, a1h, a2h, a3h, b0l, b1l);
                    mma8(C[nt][0], C[nt][1], C[nt][2], C[nt][3], a0l, a1l, a2l, a3l, b0h, b1h);
                }
            }
            __syncwarp();   // all h0 reads done before aliased h1 writes
            #pragma unroll
            for (int nt = 0; nt < 8; nt++) {
                int ch = nt * 8 + 2 * tig;
                float bA = sm[SB1 + ch], bB = sm[SB1 + ch + 1];
                sm[SH + (px0+gid)*68   + ch]     = fmaxf(C[nt][0] + bA, 0.f);
                sm[SH + (px0+gid)*68   + ch + 1] = fmaxf(C[nt][1] + bB, 0.f);
                sm[SH + (px0+gid+8)*68 + ch]     = fmaxf(C[nt][2] + bA, 0.f);
                sm[SH + (px0+gid+8)*68 + ch + 1] = fmaxf(C[nt][3] + bB, 0.f);
            }
        }
        __syncwarp();

        // ---- GEMM2: logits, 2-split (AhBh + AlBh), fused channel-max ----
        {
            float C[16][4];
            #pragma unroll
            for (int nt = 0; nt < 16; nt++)
                C[nt][0] = C[nt][1] = C[nt][2] = C[nt][3] = 0.f;

            for (int k0 = 0; k0 < 64; k0 += 8) {
                const int pp = (k0 >> 1) + tig;
                float f0 = sm[SH + (px0+gid)*68   + k0+tig];
                float f1 = sm[SH + (px0+gid+8)*68 + k0+tig];
                float f2 = sm[SH + (px0+gid)*68   + k0+tig+4];
                float f3 = sm[SH + (px0+gid+8)*68 + k0+tig+4];
                unsigned a0h = f2tf(f0), a1h = f2tf(f1), a2h = f2tf(f2), a3h = f2tf(f3);
                unsigned a0l = f2tf(f0 - __uint_as_float(a0h));
                unsigned a1l = f2tf(f1 - __uint_as_float(a1h));
                unsigned a2l = f2tf(f2 - __uint_as_float(a2h));
                unsigned a3l = f2tf(f3 - __uint_as_float(a3h));
                #pragma unroll
                for (int nt = 0; nt < 16; nt++) {
                    int nr = nt * 8 + gid;
                    float2 bh = W2H2[nr*36 + pp];
                    unsigned b0h = __float_as_uint(bh.x), b1h = __float_as_uint(bh.y);
                    mma8(C[nt][0], C[nt][1], C[nt][2], C[nt][3], a0h, a1h, a2h, a3h, b0h, b1h);
                    mma8(C[nt][0], C[nt][1], C[nt][2], C[nt][3], a0l, a1l, a2l, a3l, b0h, b1h);
                }
            }
            float mx0 = -1e30f, mx1 = -1e30f;
            #pragma unroll
            for (int nt = 0; nt < 16; nt++) {
                int ch = nt * 8 + 2 * tig;
                float bA = sm[SB2 + ch], bB = sm[SB2 + ch + 1];
                mx0 = fmaxf(mx0, fmaxf(C[nt][0] + bA, 0.f));
                mx0 = fmaxf(mx0, fmaxf(C[nt][1] + bB, 0.f));
                mx1 = fmaxf(mx1, fmaxf(C[nt][2] + bA, 0.f));
                mx1 = fmaxf(mx1, fmaxf(C[nt][3] + bB, 0.f));
            }
            mx0 = fmaxf(mx0, __shfl_xor_sync(0xffffffffu, mx0, 1));
            mx0 = fmaxf(mx0, __shfl_xor_sync(0xffffffffu, mx0, 2));
            mx1 = fmaxf(mx1, __shfl_xor_sync(0xffffffffu, mx1, 1));
            mx1 = fmaxf(mx1, __shfl_xor_sync(0xffffffffu, mx1, 2));
            if (tig == 0) {
                sm[SMX + pb*128 + px0 + gid]     = mx0;
                sm[SMX + pb*128 + px0 + gid + 8] = mx1;
            }
        }
        __syncthreads();

        // ---- softmax over 32 neighbors + weighted coord sum (warps 0-3) ----
        if (w < 4) {
            float m = sm[SMX + pb*128 + w * 32 + lane];
            float M = m;
            #pragma unroll
            for (int o = 16; o; o >>= 1) M = fmaxf(M, __shfl_xor_sync(0xffffffffu, M, o));
            float e = expf(m - M);
            float S = e;
            #pragma unroll
            for (int o = 16; o; o >>= 1) S += __shfl_xor_sync(0xffffffffu, S, o);
            float wt = e / S;

            size_t gpix = ((size_t)tile * 128 + w * 32 + lane) * 3;
            float sx = wt * g_grp[gpix + 0];
            float sy = wt * g_grp[gpix + 1];
            float sz = wt * g_grp[gpix + 2];
            #pragma unroll
            for (int o = 16; o; o >>= 1) {
                sx += __shfl_xor_sync(0xffffffffu, sx, o);
                sy += __shfl_xor_sync(0xffffffffu, sy, o);
                sz += __shfl_xor_sync(0xffffffffu, sz, o);
            }
            if (lane == 0) {
                int pt = tile * 4 + w;
                int b  = pt >> 12;
                int n  = pt & (NPTS - 1);
                out[(b*3 + 0) * NPTS + n] = sx;
                out[(b*3 + 1) * NPTS + n] = sy;
                out[(b*3 + 2) * NPTS + n] = sz;
            }
        }
        pb ^= 1;
    }
}

// ---------------- launch ----------------
extern "C" void kernel_launch(void* const* d_in, const int* in_sizes, int n_in,
                              void* d_out, int out_size)
{
    const float* p1 = (const float*)d_in[0];
    const float* p2 = (const float*)d_in[1];
    // d_in[2] = k (fixed at 16)
    const float* w0  = (const float*)d_in[3];
    const float* b0  = (const float*)d_in[4];
    const float* g0  = (const float*)d_in[5];
    const float* be0 = (const float*)d_in[6];
    const float* m0  = (const float*)d_in[7];
    const float* v0  = (const float*)d_in[8];
    const float* w1  = (const float*)d_in[9];
    const float* b1  = (const float*)d_in[10];
    const float* g1  = (const float*)d_in[11];
    const float* be1 = (const float*)d_in[12];
    const float* m1  = (const float*)d_in[13];
    const float* v1  = (const float*)d_in[14];
    const float* w2  = (const float*)d_in[15];
    const float* b2  = (const float*)d_in[16];
    const float* g2  = (const float*)d_in[17];
    const float* be2 = (const float*)d_in[18];
    const float* m2  = (const float*)d_in[19];
    const float* v2  = (const float*)d_in[20];

    cudaFuncSetAttribute(mlp_mma, cudaFuncAttributeMaxDynamicSharedMemorySize,
                         STOT * (int)sizeof(float));

    prep_k<<<48, 256>>>(w0, b0, g0, be0, m0, v0,
                        w1, b1, g1, be1, m1, v1,
                        w2, b2, g2, be2, m2, v2);

    pack_k<<<2*BATCH*NPTS/256, 256>>>(p1, p2);

    knn_w<<<dim3(NPTS/8, BATCH, 2), 256>>>(p1);

    // persistent: 2 blocks/SM on 148 SMs
    mlp_mma<<<296, 256, STOT * (int)sizeof(float)>>>((float*)d_out);
}

// round 15
// speedup vs baseline: 1.6155x; 1.0610x over previous
#include <cuda_runtime.h>
#include <math.h>

#define BATCH 4
#define NPTS  4096
#define KNN   16
#define NB    32          // 2*k neighbors per point
#define NPIX  (BATCH*NPTS*NB)
#define NTILE (NPIX/128)  // 4096 tiles of 128 pixels

// ---------------- device scratch ----------------
__device__ float4 g_feats[NPIX];        // (resi.x, resi.y, resi.z, dist) per pixel
__device__ float  g_grp[NPIX*3];        // gathered neighbor coords per pixel
__device__ float4 g_r4[2*BATCH*NPTS];   // prepacked refs: (x, y, z, x^2+y^2+z^2)

// folded weights in PAIRED tf32 layout: row stride 72 floats of (k, k+4) pairs
__device__ float  gW1hp[64*72];
__device__ float  gW2hp[128*72];
__device__ float4 gW0f[64];
__device__ float  gb0[64], gb1[64], gb2[128];

// ---------------- helpers ----------------
__device__ __forceinline__ unsigned f2tf(float x) {
    unsigned r; asm("cvt.rna.tf32.f32 %0,%1;" : "=r"(r) : "f"(x)); return r;
}
__device__ __forceinline__ void mma8(float& c0, float& c1, float& c2, float& c3,
                                     unsigned a0, unsigned a1, unsigned a2, unsigned a3,
                                     unsigned b0, unsigned b1)
{
    asm("mma.sync.aligned.m16n8k8.row.col.f32.tf32.tf32.f32 "
        "{%0,%1,%2,%3},{%4,%5,%6,%7},{%8,%9},{%0,%1,%2,%3};"
        : "+f"(c0), "+f"(c1), "+f"(c2), "+f"(c3)
        : "r"(a0), "r"(a1), "r"(a2), "r"(a3), "r"(b0), "r"(b1));
}
// paired index for weight element k (0..63): j=k>>3, tig=k&3, slot=(k>>2)&1
__device__ __forceinline__ int pidx(int nr, int k) {
    return nr * 72 + (((k >> 3) * 4 + (k & 3)) << 1) + ((k >> 2) & 1);
}

// ---------------- pack refs with their squared norm ----------------
__global__ __launch_bounds__(256) void pack_k(const float* __restrict__ p1,
                                              const float* __restrict__ p2)
{
    int i = blockIdx.x * 256 + threadIdx.x;     // 0 .. 2*BATCH*NPTS-1
    int phase = i >> 14;                        // BATCH*NPTS = 16384
    int rem   = i & 16383;
    int b     = rem >> 12;
    int r     = rem & (NPTS - 1);
    const float* P = (phase ? p2 : p1) + b * 3 * NPTS;
    float x = P[r], y = P[NPTS + r], z = P[2*NPTS + r];
    g_r4[i] = make_float4(x, y, z, fmaf(x, x, fmaf(y, y, z * z)));
}

// ---------------- fold BN + split weights into paired tf32 (parallel) ----------------
__global__ __launch_bounds__(256) void prep_k(
    const float* __restrict__ w0, const float* __restrict__ b0,
    const float* __restrict__ g0, const float* __restrict__ be0,
    const float* __restrict__ m0, const float* __restrict__ v0,
    const float* __restrict__ w1, const float* __restrict__ b1,
    const float* __restrict__ g1, const float* __restrict__ be1,
    const float* __restrict__ m1, const float* __restrict__ v1,
    const float* __restrict__ w2, const float* __restrict__ b2,
    const float* __restrict__ g2, const float* __restrict__ be2,
    const float* __restrict__ m2, const float* __restrict__ v2)
{
    int t = threadIdx.x;
    if (blockIdx.x == 0) {
        if (t < 64) {
            float s = g0[t] * rsqrtf(v0[t] + 1e-3f);
            float4 w; w.x = w0[t*4+0]*s; w.y = w0[t*4+1]*s; w.z = w0[t*4+2]*s; w.w = w0[t*4+3]*s;
            gW0f[t] = w;
            gb0[t] = (b0[t] - m0[t]) * s + be0[t];
            float ss = g1[t] * rsqrtf(v1[t] + 1e-3f);
            gb1[t] = (b1[t] - m1[t]) * ss + be1[t];
        }
        if (t < 128) {
            float ss = g2[t] * rsqrtf(v2[t] + 1e-3f);
            gb2[t] = (b2[t] - m2[t]) * ss + be2[t];
        }
    }
    int i = blockIdx.x * 256 + t;   // W1: 4096 elems, W2: 8192 elems
    if (i < 4096) {
        int nr = i >> 6, k = i & 63;
        float s = g1[nr] * rsqrtf(v1[nr] + 1e-3f);
        float wv = w1[nr*64 + k] * s;
        gW1hp[pidx(nr, k)] = __uint_as_float(f2tf(wv));
    } else if (i < 4096 + 8192) {
        int j = i - 4096;
        int nr = j >> 6, k = j & 63;
        float s = g2[nr] * rsqrtf(v2[nr] + 1e-3f);
        float wv = w2[nr*64 + k] * s;
        gW2hp[pidx(nr, k)] = __uint_as_float(f2tf(wv));
    }
}

// ---------------- KNN: one WARP per query, dual-ref scan + distributed top-16 ----------------
// Lane i (i<16) holds slot i of the sorted-ascending top-16. Each lane evaluates
// TWO refs per round (64-ref batches), amortizing shfl/ballot/loop overhead.
// Inserts: warp shift-and-place, self-guarding (no-op when c >= dl[15]).
#define KTILE 2048

__global__ __launch_bounds__(256) void knn_w(const float* __restrict__ p1)
{
    const int lane  = threadIdx.x & 31;
    const int wid   = threadIdx.x >> 5;
    const int b     = blockIdx.y;
    const int phase = blockIdx.z;
    const int n     = blockIdx.x * 8 + wid;       // query index

    const float* Q = p1 + b * 3 * NPTS;
    const float qx = Q[n], qy = Q[NPTS + n], qz = Q[2*NPTS + n];

    const float4* __restrict__ R4 = g_r4 + (phase * BATCH + b) * NPTS;

    const float INF = __int_as_float(0x7f800000);
    float dl = INF;   // slot (lane) value, v-domain
    int   il = 0;     // slot (lane) ref index

    __shared__ float4 sref[KTILE];

    for (int t0 = 0; t0 < NPTS; t0 += KTILE) {
        for (int i = threadIdx.x; i < KTILE; i += 256)
            sref[i] = R4[t0 + i];
        __syncthreads();

        for (int tt = 0; tt < KTILE / 64; tt++) {
            const int tbase = t0 + tt * 64;
            float4 r0 = sref[tt * 64 + lane];
            float4 r1 = sref[tt * 64 + 32 + lane];
            // compare in the v = rr - 2*dot domain (d2 = v + qq, same ordering)
            float v0 = fmaf(-2.f, fmaf(qx, r0.x, fmaf(qy, r0.y, qz * r0.z)), r0.w);
            float v1 = fmaf(-2.f, fmaf(qx, r1.x, fmaf(qy, r1.y, qz * r1.z)), r1.w);
            float thr = __shfl_sync(0xffffffffu, dl, 15);
            unsigned m0 = __ballot_sync(0xffffffffu, v0 < thr);
            unsigned m1 = __ballot_sync(0xffffffffu, v1 < thr);
            while (m0) {
                int src = __ffs(m0) - 1;
                m0 &= m0 - 1;
                float c  = __shfl_sync(0xffffffffu, v0, src);
                int   ci = tbase + src;
                float up  = __shfl_up_sync(0xffffffffu, dl, 1);
                int   upi = __shfl_up_sync(0xffffffffu, il, 1);
                bool  p   = c < dl;
                unsigned bp = __ballot_sync(0xffffffffu, p);
                bool  pu  = lane ? ((bp >> (lane - 1)) & 1u) : false;
                dl = p ? (pu ? up  : c ) : dl;
                il = p ? (pu ? upi : ci) : il;
            }
            while (m1) {
                int src = __ffs(m1) - 1;
                m1 &= m1 - 1;
                float c  = __shfl_sync(0xffffffffu, v1, src);
                int   ci = tbase + 32 + src;
                float up  = __shfl_up_sync(0xffffffffu, dl, 1);
                int   upi = __shfl_up_sync(0xffffffffu, il, 1);
                bool  p   = c < dl;
                unsigned bp = __ballot_sync(0xffffffffu, p);
                bool  pu  = lane ? ((bp >> (lane - 1)) & 1u) : false;
                dl = p ? (pu ? up  : c ) : dl;
                il = p ? (pu ? upi : ci) : il;
            }
        }
        __syncthreads();
    }

    if (lane < KNN) {
        float4 rv = R4[il];
        float dx = rv.x - qx, dy = rv.y - qy, dz = rv.z - qz;
        float d  = sqrtf(fmaxf(dx*dx + dy*dy + dz*dz, 1e-12f));
        size_t base = ((size_t)(b * NPTS + n)) * NB + phase * KNN + lane;
        g_feats[base] = make_float4(dx, dy, dz, d);
        g_grp[base*3 + 0] = rv.x;
        g_grp[base*3 + 1] = rv.y;
        g_grp[base*3 + 2] = rv.z;
    }
}

// ---------------- MLP via tensor cores, persistent grid, 2 blocks/SM ----------------
// block = 256 threads = 8 warps; tile = 128 pixels (4 points); warp w owns rows
// [16w,16w+16) (warp-private; H1 aliases H0). Paired float2 weight layout.
// GEMM1: 2-split (AhBh + AlBh). GEMM2: 2-split (AhBh + AlBh).
// smem float offsets:
#define SW1H 0          // 64 x 72
#define SW2H 4608       // 128 x 72
#define SH   13824      // h0 / h1 aliased (128 x stride 68)
#define SW0  22528      // float4[64]
#define SB0  22784
#define SB1  22848
#define SB2  22912
#define SMX  23040      // double-buffered 2 x 128
#define STOT 23296      // floats -> 93184 bytes

__global__ __launch_bounds__(256, 2) void mlp_mma(float* __restrict__ out)
{
    extern __shared__ float sm[];
    const int t    = threadIdx.x;
    const int lane = t & 31;
    const int w    = t >> 5;

    // ---- stage weights once per block ----
    {
        float4* s4 = (float4*)sm;
        const float4* a = (const float4*)gW1hp;
        for (int i = t; i < 64*72/4; i += 256)
            s4[SW1H/4 + i] = a[i];
        const float4* c = (const float4*)gW2hp;
        for (int i = t; i < 128*72/4; i += 256)
            s4[SW2H/4 + i] = c[i];
        if (t < 64) {
            s4[SW0/4 + t] = gW0f[t];
            sm[SB0 + t] = gb0[t];
            sm[SB1 + t] = gb1[t];
        }
        if (t < 128) sm[SB2 + t] = gb2[t];
    }
    __syncthreads();

    const int gid = lane >> 2;    // 0..7
    const int tig = lane & 3;     // 0..3
    const int px0 = w * 16;
    int pb = 0;                   // MX buffer parity

    const float2* W1H2 = (const float2*)(sm + SW1H);
    const float2* W2H2 = (const float2*)(sm + SW2H);

    for (int tile = blockIdx.x; tile < NTILE; tile += gridDim.x) {

        // ---- layer 0 (warp-local): lane handles row px0+(lane&15), half lane>>4 ----
        {
            int rloc = lane & 15, half = lane >> 4;
            int row  = px0 + rloc;
            float4 x = g_feats[(size_t)tile * 128 + row];
            const float4* s4 = (const float4*)sm;
            float* hrow = sm + SH + row * 68 + half * 32;
            #pragma unroll 4
            for (int c = 0; c < 32; c++) {
                int ch = half * 32 + c;
                float4 wv = s4[SW0/4 + ch];
                float a = fmaf(wv.x, x.x, fmaf(wv.y, x.y,
                          fmaf(wv.z, x.z, fmaf(wv.w, x.w, sm[SB0 + ch]))));
                hrow[c] = fmaxf(a, 0.f);
            }
        }
        __syncwarp();

        // ---- GEMM1: h1 = relu(h0 @ W1^T + b1), 2-split, H1 aliases H0 ----
        {
            float C[8][4];
            #pragma unroll
            for (int nt = 0; nt < 8; nt++)
                C[nt][0] = C[nt][1] = C[nt][2] = C[nt][3] = 0.f;

            for (int k0 = 0; k0 < 64; k0 += 8) {
                const int pp = (k0 >> 1) + tig;     // paired index within row
                float f0 = sm[SH + (px0+gid)*68   + k0+tig];
                float f1 = sm[SH + (px0+gid+8)*68 + k0+tig];
                float f2 = sm[SH + (px0+gid)*68   + k0+tig+4];
                float f3 = sm[SH + (px0+gid+8)*68 + k0+tig+4];
                unsigned a0h = f2tf(f0), a1h = f2tf(f1), a2h = f2tf(f2), a3h = f2tf(f3);
                unsigned a0l = f2tf(f0 - __uint_as_float(a0h));
                unsigned a1l = f2tf(f1 - __uint_as_float(a1h));
                unsigned a2l = f2tf(f2 - __uint_as_float(a2h));
                unsigned a3l = f2tf(f3 - __uint_as_float(a3h));
                #pragma unroll
                for (int nt = 0; nt < 8; nt++) {
                    int nr = nt * 8 + gid;
                    float2 bh = W1H2[nr*36 + pp];
                    unsigned b0h = __float_as_uint(bh.x), b1h = __float_as_uint(bh.y);
                    mma8(C[nt][0], C[nt][1], C[nt][2], C[nt][3], a0h, a1h, a2h, a3h, b0h, b1h);
                    mma8(C[nt][0], C[nt][1], C[nt][2], C[nt][3], a0l, a1l, a2l, a3l, b0h, b1h);
                }
            }
            __syncwarp();   // all h0 reads done before aliased h1 writes
            #pragma unroll
            for (int nt = 0; nt < 8; nt++) {
                int ch = nt * 8 + 2 * tig;
                float bA = sm[SB1 + ch], bB = sm[SB1 + ch + 1];
                sm[SH + (px0+gid)*68   + ch]     = fmaxf(C[nt][0] + bA, 0.f);
                sm[SH + (px0+gid)*68   + ch + 1] = fmaxf(C[nt][1] + bB, 0.f);
                sm[SH + (px0+gid+8)*68 + ch]     = fmaxf(C[nt][2] + bA, 0.f);
                sm[SH + (px0+gid+8)*68 + ch + 1] = fmaxf(C[nt][3] + bB, 0.f);
            }
        }
        __syncwarp();

        // ---- GEMM2: logits, 2-split (AhBh + AlBh), fused channel-max ----
        {
            float C[16][4];
            #pragma unroll
            for (int nt = 0; nt < 16; nt++)
                C[nt][0] = C[nt][1] = C[nt][2] = C[nt][3] = 0.f;

            for (int k0 = 0; k0 < 64; k0 += 8) {
                const int pp = (k0 >> 1) + tig;
                float f0 = sm[SH + (px0+gid)*68   + k0+tig];
                float f1 = sm[SH + (px0+gid+8)*68 + k0+tig];
                float f2 = sm[SH + (px0+gid)*68   + k0+tig+4];
                float f3 = sm[SH + (px0+gid+8)*68 + k0+tig+4];
                unsigned a0h = f2tf(f0), a1h = f2tf(f1), a2h = f2tf(f2), a3h = f2tf(f3);
                unsigned a0l = f2tf(f0 - __uint_as_float(a0h));
                unsigned a1l = f2tf(f1 - __uint_as_float(a1h));
                unsigned a2l = f2tf(f2 - __uint_as_float(a2h));
                unsigned a3l = f2tf(f3 - __uint_as_float(a3h));
                #pragma unroll
                for (int nt = 0; nt < 16; nt++) {
                    int nr = nt * 8 + gid;
                    float2 bh = W2H2[nr*36 + pp];
                    unsigned b0h = __float_as_uint(bh.x), b1h = __float_as_uint(bh.y);
                    mma8(C[nt][0], C[nt][1], C[nt][2], C[nt][3], a0h, a1h, a2h, a3h, b0h, b1h);
                    mma8(C[nt][0], C[nt][1], C[nt][2], C[nt][3], a0l, a1l, a2l, a3l, b0h, b1h);
                }
            }
            float mx0 = -1e30f, mx1 = -1e30f;
            #pragma unroll
            for (int nt = 0; nt < 16; nt++) {
                int ch = nt * 8 + 2 * tig;
                float bA = sm[SB2 + ch], bB = sm[SB2 + ch + 1];
                mx0 = fmaxf(mx0, fmaxf(C[nt][0] + bA, 0.f));
                mx0 = fmaxf(mx0, fmaxf(C[nt][1] + bB, 0.f));
                mx1 = fmaxf(mx1, fmaxf(C[nt][2] + bA, 0.f));
                mx1 = fmaxf(mx1, fmaxf(C[nt][3] + bB, 0.f));
            }
            mx0 = fmaxf(mx0, __shfl_xor_sync(0xffffffffu, mx0, 1));
            mx0 = fmaxf(mx0, __shfl_xor_sync(0xffffffffu, mx0, 2));
            mx1 = fmaxf(mx1, __shfl_xor_sync(0xffffffffu, mx1, 1));
            mx1 = fmaxf(mx1, __shfl_xor_sync(0xffffffffu, mx1, 2));
            if (tig == 0) {
                sm[SMX + pb*128 + px0 + gid]     = mx0;
                sm[SMX + pb*128 + px0 + gid + 8] = mx1;
            }
        }
        __syncthreads();

        // ---- softmax over 32 neighbors + weighted coord sum (warps 0-3) ----
        if (w < 4) {
            float m = sm[SMX + pb*128 + w * 32 + lane];
            float M = m;
            #pragma unroll
            for (int o = 16; o; o >>= 1) M = fmaxf(M, __shfl_xor_sync(0xffffffffu, M, o));
            float e = expf(m - M);
            float S = e;
            #pragma unroll
            for (int o = 16; o; o >>= 1) S += __shfl_xor_sync(0xffffffffu, S, o);
            float wt = e / S;

            size_t gpix = ((size_t)tile * 128 + w * 32 + lane) * 3;
            float sx = wt * g_grp[gpix + 0];
            float sy = wt * g_grp[gpix + 1];
            float sz = wt * g_grp[gpix + 2];
            #pragma unroll
            for (int o = 16; o; o >>= 1) {
                sx += __shfl_xor_sync(0xffffffffu, sx, o);
                sy += __shfl_xor_sync(0xffffffffu, sy, o);
                sz += __shfl_xor_sync(0xffffffffu, sz, o);
            }
            if (lane == 0) {
                int pt = tile * 4 + w;
                int b  = pt >> 12;
                int n  = pt & (NPTS - 1);
                out[(b*3 + 0) * NPTS + n] = sx;
                out[(b*3 + 1) * NPTS + n] = sy;
                out[(b*3 + 2) * NPTS + n] = sz;
            }
        }
        pb ^= 1;
    }
}

// ---------------- launch ----------------
extern "C" void kernel_launch(void* const* d_in, const int* in_sizes, int n_in,
                              void* d_out, int out_size)
{
    const float* p1 = (const float*)d_in[0];
    const float* p2 = (const float*)d_in[1];
    // d_in[2] = k (fixed at 16)
    const float* w0  = (const float*)d_in[3];
    const float* b0  = (const float*)d_in[4];
    const float* g0  = (const float*)d_in[5];
    const float* be0 = (const float*)d_in[6];
    const float* m0  = (const float*)d_in[7];
    const float* v0  = (const float*)d_in[8];
    const float* w1  = (const float*)d_in[9];
    const float* b1  = (const float*)d_in[10];
    const float* g1  = (const float*)d_in[11];
    const float* be1 = (const float*)d_in[12];
    const float* m1  = (const float*)d_in[13];
    const float* v1  = (const float*)d_in[14];
    const float* w2  = (const float*)d_in[15];
    const float* b2  = (const float*)d_in[16];
    const float* g2  = (const float*)d_in[17];
    const float* be2 = (const float*)d_in[18];
    const float* m2  = (const float*)d_in[19];
    const float* v2  = (const float*)d_in[20];

    cudaFuncSetAttribute(mlp_mma, cudaFuncAttributeMaxDynamicSharedMemorySize,
                         STOT * (int)sizeof(float));

    prep_k<<<48, 256>>>(w0, b0, g0, be0, m0, v0,
                        w1, b1, g1, be1, m1, v1,
                        w2, b2, g2, be2, m2, v2);

    pack_k<<<2*BATCH*NPTS/256, 256>>>(p1, p2);

    knn_w<<<dim3(NPTS/8, BATCH, 2), 256>>>(p1);

    // persistent: 2 blocks/SM on 148 SMs
    mlp_mma<<<296, 256, STOT * (int)sizeof(float)>>>((float*)d_out);
}